// round 13
// baseline (speedup 1.0000x reference)
#include <cuda_runtime.h>
#include <cuda_fp16.h>
#include <cstdint>

#define B_SZ  4096
#define IN_F  256
#define OUT_F 256
#define HYP   128
#define BM    128
#define BN    64

// ---------------- device scratch (allocation-free rule) ----------------
__device__ __align__(256) float  g_hgT[HYP * B_SZ];                    // [h][b] fp32
__device__ __align__(256) __half g_hb16[B_SZ * HYP];                   // [b][h]
__device__ __align__(256) __half g_x16[B_SZ * IN_F];                   // [b][i]
__device__ __align__(256) __half g_w2g16[(size_t)HYP * OUT_F * IN_F];  // [h][o][i]
__device__ __align__(256) __half g_b2g16[OUT_F * IN_F];                // [o][i]
__device__ __align__(256) __half g_w2bT16[OUT_F * HYP];                // [o][k]

// ---------------- PTX helpers (sm_80+ baseline ISA only) ----------------
__device__ __forceinline__ uint32_t smem_u32(const void* p) {
    uint32_t a;
    asm("{ .reg .u64 t; cvta.to.shared.u64 t, %1; cvt.u32.u64 %0, t; }" : "=r"(a) : "l"(p));
    return a;
}
#define CP16(dst, src) \
    asm volatile("cp.async.cg.shared.global [%0], [%1], 16;" :: "r"(dst), "l"(src) : "memory")
#define CP_COMMIT() asm volatile("cp.async.commit_group;" ::: "memory")
#define CP_WAIT(n)  asm volatile("cp.async.wait_group %0;" :: "n"(n) : "memory")

__device__ __forceinline__ void ldsm4(uint32_t* r, uint32_t addr) {
    asm volatile("ldmatrix.sync.aligned.m8n8.x4.shared.b16 {%0,%1,%2,%3}, [%4];"
        : "=r"(r[0]), "=r"(r[1]), "=r"(r[2]), "=r"(r[3]) : "r"(addr));
}
// d += A(16x16) * B(16x8)  fp16 in, fp32 accum
__device__ __forceinline__ void mma_16816(float* d, const uint32_t* a, const uint32_t* b) {
    asm volatile(
        "mma.sync.aligned.m16n8k16.row.col.f32.f16.f16.f32 "
        "{%0,%1,%2,%3}, {%4,%5,%6,%7}, {%8,%9}, {%0,%1,%2,%3};"
        : "+f"(d[0]), "+f"(d[1]), "+f"(d[2]), "+f"(d[3])
        : "r"(a[0]), "r"(a[1]), "r"(a[2]), "r"(a[3]), "r"(b[0]), "r"(b[1]));
}
// d += A(16x8) * B(8x8)  tf32 in, fp32 accum
__device__ __forceinline__ void mma_tf32(float* d, const uint32_t* a, const uint32_t* b) {
    asm volatile(
        "mma.sync.aligned.m16n8k8.row.col.f32.tf32.tf32.f32 "
        "{%0,%1,%2,%3}, {%4,%5,%6,%7}, {%8,%9}, {%0,%1,%2,%3};"
        : "+f"(d[0]), "+f"(d[1]), "+f"(d[2]), "+f"(d[3])
        : "r"(a[0]), "r"(a[1]), "r"(a[2]), "r"(a[3]), "r"(b[0]), "r"(b[1]));
}
__device__ __forceinline__ uint32_t f2tf32(float f) {
    uint32_t r;
    asm("cvt.rna.tf32.f32 %0, %1;" : "=r"(r) : "f"(f));
    return r;
}

// ---------------- kernel 0: prep ----------------
// blocks 0..127:   hidden via tf32 MMA (32 batch rows each) + x16 write
// blocks 128..1151: W2g/b2g fp16 converts + W2b transpose (ILP-2 grid stride)
#define XS_LD 260   // padded fp32 row stride: bank = (4*tq+tr)%32 unique, 16B-aligned rows
__global__ __launch_bounds__(256) void prep_kernel(
    const float* __restrict__ x,
    const float* __restrict__ W1g, const float* __restrict__ b1g,
    const float* __restrict__ W1b, const float* __restrict__ b1b,
    const float* __restrict__ W2g, const float* __restrict__ b2g,
    const float* __restrict__ W2b)
{
    if (blockIdx.x < 128) {
        // ---- hidden: hg/hb for 32 batch rows via tf32 tensor cores ----
        __shared__ __align__(16) float xs[32 * XS_LD];
        const int b0 = blockIdx.x * 32;
        const int tid = threadIdx.x;
        const int lane = tid & 31;
        const int wid = tid >> 5;
        const int wm = wid & 1;       // m16 half of the 32-row tile
        const int wn = wid >> 1;      // 0,1: W1g n64 ranges; 2,3: W1b
        const int tq = lane >> 2;     // 0..7
        const int tr = lane & 3;      // 0..3

        // load x tile (fp32) into padded smem + emit x16 on the way
        for (int idx = tid; idx < 32 * 64; idx += 256) {
            int row = idx >> 6, c4 = idx & 63;
            float4 v = ((const float4*)(x + (size_t)(b0 + row) * IN_F))[c4];
            *(float4*)(xs + row * XS_LD + c4 * 4) = v;
            __half2* d2 = (__half2*)(g_x16 + (size_t)(b0 + row) * IN_F + c4 * 4);
            d2[0] = __floats2half2_rn(v.x, v.y);
            d2[1] = __floats2half2_rn(v.z, v.w);
        }
        __syncthreads();

        const float* W  = (wn < 2) ? W1g : W1b;
        const float* bv = (wn < 2) ? b1g : b1b;
        const int nbase = (wn & 1) * 64;

        float acc[8][4];
#pragma unroll
        for (int nt = 0; nt < 8; nt++)
#pragma unroll
            for (int e = 0; e < 4; e++) acc[nt][e] = 0.f;

        const int ar0 = wm * 16 + tq;          // A rows ar0, ar0+8
#pragma unroll 4
        for (int k0 = 0; k0 < IN_F; k0 += 8) {
            uint32_t a[4];
            a[0] = f2tf32(xs[(ar0)     * XS_LD + k0 + tr]);
            a[1] = f2tf32(xs[(ar0 + 8) * XS_LD + k0 + tr]);
            a[2] = f2tf32(xs[(ar0)     * XS_LD + k0 + tr + 4]);
            a[3] = f2tf32(xs[(ar0 + 8) * XS_LD + k0 + tr + 4]);
#pragma unroll
            for (int nt = 0; nt < 8; nt++) {
                int nb = nbase + nt * 8 + tq;
                uint32_t b[2];
                b[0] = f2tf32(W[(k0 + tr)     * HYP + nb]);
                b[1] = f2tf32(W[(k0 + tr + 4) * HYP + nb]);
                mma_tf32(acc[nt], a, b);
            }
        }

        // epilogue: +bias, relu, store (hg transposed fp32; hb row-major fp16)
        const int r0 = b0 + wm * 16 + tq;
#pragma unroll
        for (int nt = 0; nt < 8; nt++) {
            int h0 = nbase + nt * 8 + tr * 2;
            float bb0 = bv[h0], bb1 = bv[h0 + 1];
            float v00 = fmaxf(acc[nt][0] + bb0, 0.f);
            float v01 = fmaxf(acc[nt][1] + bb1, 0.f);
            float v10 = fmaxf(acc[nt][2] + bb0, 0.f);
            float v11 = fmaxf(acc[nt][3] + bb1, 0.f);
            if (wn < 2) {
                g_hgT[(size_t)(h0)     * B_SZ + r0]     = v00;
                g_hgT[(size_t)(h0 + 1) * B_SZ + r0]     = v01;
                g_hgT[(size_t)(h0)     * B_SZ + r0 + 8] = v10;
                g_hgT[(size_t)(h0 + 1) * B_SZ + r0 + 8] = v11;
            } else {
                *(__half2*)(g_hb16 + (size_t)(r0)     * HYP + h0) = __floats2half2_rn(v00, v01);
                *(__half2*)(g_hb16 + (size_t)(r0 + 8) * HYP + h0) = __floats2half2_rn(v10, v11);
            }
        }
    } else {
        const int gtid = (blockIdx.x - 128) * 256 + threadIdx.x;  // 0..262143
        if (gtid < OUT_F * HYP) {                                 // W2b transpose
            int o = gtid >> 7, k = gtid & 127;
            g_w2bT16[gtid] = __float2half_rn(W2b[k * OUT_F + o]);
        }
        // float4-granular converts: W2g + b2g (x handled by hidden blocks)
        const int64_t N1 = (int64_t)HYP * OUT_F * IN_F / 4;
        const int64_t N2 = N1 + (int64_t)OUT_F * IN_F / 4;
        const int64_t stride = (int64_t)1024 * 256;
        auto cvt1 = [&](int64_t i) {
            const float4* src; __half* dst; int64_t j;
            if (i < N1) { src = (const float4*)W2g; dst = g_w2g16; j = i; }
            else        { src = (const float4*)b2g; dst = g_b2g16; j = i - N1; }
            float4 v = src[j];
            __half2* d2 = (__half2*)(dst + j * 4);
            d2[0] = __floats2half2_rn(v.x, v.y);
            d2[1] = __floats2half2_rn(v.z, v.w);
        };
        int64_t i = gtid;
        for (; i + stride < N2; i += 2 * stride) {   // two independent per iter
            cvt1(i);
            cvt1(i + stride);
        }
        if (i < N2) cvt1(i);
    }
}

// ---------------- kernel 1: mma.sync main (proven 217us variant, unchanged) --
// smem: X 128x512B swz (64KB) | HB 128x256B swz (32KB)
//       B 3x 64x512B (96KB) | S 4x 512B scale buffers
#define X_OFF   0
#define HB_OFF  65536
#define B_OFF   98304
#define S_OFF   196608
#define SMEM_TOTAL 198656

__global__ __launch_bounds__(256, 1) void main_kernel(
    float* __restrict__ out, const float* __restrict__ b2b)
{
    extern __shared__ __align__(1024) char smem[];
    const uint32_t sb = smem_u32(smem);
    const int tid = threadIdx.x;
    const int lane = tid & 31;
    const int wid = tid >> 5;
    const int wm = wid & 3;      // warp M position (x32)
    const int wn = wid >> 2;     // warp N position (x32)
    const int b0 = blockIdx.x * BM;
    const int o0 = blockIdx.y * BN;

    // B-tile (buffer hh%3) + hg scale (buffer hh&3) prefetch; one commit group always
    auto issueB = [&](int hh) {
        if (hh <= 129) {
            uint32_t dbuf = sb + B_OFF + (uint32_t)(hh % 3) * 32768;
            const __half* src; int nsh;
            if (hh < 128)       { src = g_w2g16 + (size_t)hh * OUT_F * IN_F + (size_t)o0 * IN_F; nsh = 5; }
            else if (hh == 128) { src = g_b2g16 + (size_t)o0 * IN_F; nsh = 5; }
            else                { src = g_w2bT16 + (size_t)o0 * HYP; nsh = 4; }
            int ldh = 1 << (nsh + 3);
            int msk = (1 << nsh) - 1;
            int tot = 64 << nsh;
            for (int idx = tid; idx < tot; idx += 256) {
                int row = idx >> nsh, k8 = idx & msk;
                CP16(dbuf + row * 512 + (uint32_t)((k8 ^ (row & 7)) << 4),
                     src + (size_t)row * ldh + k8 * 8);
            }
            if (hh < 128 && tid < 32)
                CP16(sb + S_OFF + (uint32_t)(hh & 3) * 512 + tid * 16,
                     g_hgT + (size_t)hh * B_SZ + b0 + tid * 4);
        }
        CP_COMMIT();
    };

    // ---- prologue: g0 = X + HB; g1 = B0 + S0; g2 = B1 + S1 ----
    for (int idx = tid; idx < 128 * 32; idx += 256) {
        int row = idx >> 5, k8 = idx & 31;
        CP16(sb + X_OFF + row * 512 + (uint32_t)((k8 ^ (row & 7)) << 4),
             g_x16 + (size_t)(b0 + row) * IN_F + k8 * 8);
    }
    for (int idx = tid; idx < 128 * 16; idx += 256) {
        int row = idx >> 4, k8 = idx & 15;
        CP16(sb + HB_OFF + row * 256 + (uint32_t)((k8 ^ (row & 7)) << 4),
             g_hb16 + (size_t)(b0 + row) * HYP + k8 * 8);
    }
    CP_COMMIT();
    issueB(0);
    issueB(1);

    // ---- per-thread fragment addressing ----
    const uint32_t a_row = (uint32_t)(wm * 32 + (lane & 15));
    const uint32_t a_sw  = (uint32_t)(lane & 7);
    const uint32_t a_hi  = (uint32_t)(lane >> 4);
    uint32_t b_off[4];
#pragma unroll
    for (int nn = 0; nn < 4; nn++)
        b_off[nn] = (uint32_t)(wn * 32 + nn * 8 + (lane & 7)) * 512;
    const uint32_t b_sw = (uint32_t)(lane & 7);
    const uint32_t b_hi = (uint32_t)(lane >> 3);

    float c[2][4][4];
    float p0[2][4][4], p1[2][4][4];
#pragma unroll
    for (int mf = 0; mf < 2; mf++)
#pragma unroll
        for (int nn = 0; nn < 4; nn++)
#pragma unroll
            for (int e = 0; e < 4; e++) {
                c[mf][nn][e] = 0.f; p0[mf][nn][e] = 0.f; p1[mf][nn][e] = 0.f;
            }

    const uint32_t xb  = sb + X_OFF;
    const uint32_t hbb = sb + HB_OFF;

    // one k32 step: 8 LDSM.x4 + 16 MMA into pc
    auto do_k32 = [&](uint32_t abase, uint32_t rs, uint32_t bbase, int k32,
                      float (&pc)[2][4][4]) {
        uint32_t Af[2][2][4];
#pragma unroll
        for (int mf = 0; mf < 2; mf++)
#pragma unroll
            for (int kr = 0; kr < 2; kr++) {
                uint32_t k8 = (uint32_t)(k32 * 4 + kr * 2) + a_hi;
                ldsm4(Af[mf][kr], abase + (a_row + (uint32_t)mf * 16) * rs + ((k8 ^ a_sw) << 4));
            }
        uint32_t Bf[4][4];
#pragma unroll
        for (int nn = 0; nn < 4; nn++) {
            uint32_t k8 = (uint32_t)(k32 * 4) + b_hi;
            ldsm4(Bf[nn], bbase + b_off[nn] + ((k8 ^ b_sw) << 4));
        }
#pragma unroll
        for (int mf = 0; mf < 2; mf++)
#pragma unroll
            for (int nn = 0; nn < 4; nn++) {
                mma_16816(pc[mf][nn], Af[mf][0], &Bf[nn][0]);
                mma_16816(pc[mf][nn], Af[mf][1], &Bf[nn][2]);
            }
    };

    // epilogue tile (mf,nn) of previous iteration: c += s*pp, pp = 0
    auto epi_tile = [&](int mf, int nn, float (&pp)[2][4][4], const float* s2) {
#pragma unroll
        for (int e = 0; e < 4; e++) {
            c[mf][nn][e] = fmaf(s2[mf * 2 + (e >> 1)], pp[mf][nn][e], c[mf][nn][e]);
            pp[mf][nn][e] = 0.f;
        }
    };

    // one h-iteration: compute h into pc, interleave epilogue of h-1 from pp
    auto iter = [&](int h, float (&pc)[2][4][4], float (&pp)[2][4][4]) {
        CP_WAIT(1);
        __syncthreads();
        float s2[4] = {1.f, 1.f, 1.f, 1.f};
        if (h >= 1 && h <= 128) {
            const float* ss = (const float*)(smem + S_OFF + (size_t)((h - 1) & 3) * 512);
#pragma unroll
            for (int mf = 0; mf < 2; mf++)
#pragma unroll
                for (int g = 0; g < 2; g++)
                    s2[mf * 2 + g] = ss[wm * 32 + mf * 16 + g * 8 + (lane >> 2)];
        }
        issueB(h + 2);
        uint32_t bbase = sb + B_OFF + (uint32_t)(h % 3) * 32768;
        if (h != 129) {
#pragma unroll
            for (int k32 = 0; k32 < 8; k32++) {
                do_k32(xb, 512u, bbase, k32, pc);
                if (h > 0) epi_tile(k32 >> 2, k32 & 3, pp, s2);
            }
        } else {
#pragma unroll
            for (int k32 = 0; k32 < 4; k32++) {
                do_k32(hbb, 256u, bbase, k32, pc);
                epi_tile(0, k32, pp, s2);
                epi_tile(1, k32, pp, s2);
            }
        }
    };

    // ---- mainloop: h<128 W2g[h] (scaled); 128 b2g (s=1); 129 hb@W2bT (s=1) ----
#pragma unroll 1
    for (int h = 0; h < 130; h += 2) {
        iter(h,     p0, p1);
        iter(h + 1, p1, p0);
    }
    // tail: epilogue of h=129 (in p1), s = 1
#pragma unroll
    for (int mf = 0; mf < 2; mf++)
#pragma unroll
        for (int nn = 0; nn < 4; nn++)
#pragma unroll
            for (int e = 0; e < 4; e++)
                c[mf][nn][e] += p1[mf][nn][e];

    // ---- store: out = C + b2b ----
    const int r_base = b0 + wm * 32 + (lane >> 2);
    const int c_base = o0 + wn * 32 + (lane & 3) * 2;
#pragma unroll
    for (int mf = 0; mf < 2; mf++)
#pragma unroll
        for (int nn = 0; nn < 4; nn++) {
            float2 bb2 = *(const float2*)(b2b + c_base + nn * 8);
#pragma unroll
            for (int g = 0; g < 2; g++) {
                int row = r_base + mf * 16 + g * 8;
                float2 v;
                v.x = c[mf][nn][g * 2 + 0] + bb2.x;
                v.y = c[mf][nn][g * 2 + 1] + bb2.y;
                *(float2*)(out + (size_t)row * OUT_F + c_base + nn * 8) = v;
            }
        }
}

// ---------------- launch ----------------
extern "C" void kernel_launch(void* const* d_in, const int* in_sizes, int n_in,
                              void* d_out, int out_size)
{
    const float* x   = (const float*)d_in[0];
    const float* W1g = (const float*)d_in[1];
    const float* b1g = (const float*)d_in[2];
    const float* W2g = (const float*)d_in[3];
    const float* b2g = (const float*)d_in[4];
    const float* W1b = (const float*)d_in[5];
    const float* b1b = (const float*)d_in[6];
    const float* W2b = (const float*)d_in[7];
    const float* b2b = (const float*)d_in[8];
    float* out = (float*)d_out;

    cudaFuncSetAttribute(main_kernel, cudaFuncAttributeMaxDynamicSharedMemorySize, SMEM_TOTAL);

    prep_kernel<<<1152, 256>>>(x, W1g, b1g, W1b, b1b, W2g, b2g, W2b);
    dim3 grid(B_SZ / BM, OUT_F / BN);
    main_kernel<<<grid, 256, SMEM_TOTAL>>>(out, b2b);
}